// round 7
// baseline (speedup 1.0000x reference)
#include <cuda_runtime.h>
#include <cuda_bf16.h>
#include <cstdint>

#define DT2 1.0e-6f

// ---------------- device scratch (no allocations allowed) ----------------
__device__ float g_acc[4096 * 64];   // [row*64+s], zeroed each launch, atomic-accumulated

static __device__ __forceinline__ uint32_t smem_u32(const void* p) {
    uint32_t a;
    asm("{ .reg .u64 t; cvta.to.shared.u64 t, %1; cvt.u32.u64 %0, t; }"
        : "=r"(a) : "l"(p));
    return a;
}

// ===================== kernel 1: bf16 mma.sync GEMM =====================
// acc[row0:+128][0:64] += deno[row0:+128, k0:+256] @ X[k0:+256, 0:64]   (atomics)
// grid (32, 16): blockIdx.x = M tile (128 rows), blockIdx.y = K split (256 K)
// 256 threads = 8 warps, warp grid 4(M) x 2(N), warp tile 32x32.
// Kc = 64 per chunk (4 chunks), double buffered, register prefetch.
static constexpr uint32_t TSTRIDE = 144;                  // bytes per row
static constexpr uint32_t ABUF = 128 * TSTRIDE;           // 18432
static constexpr uint32_t BBUF = 64 * TSTRIDE;            // 9216
static constexpr uint32_t SMEM_REQ = 2 * ABUF + 2 * BBUF; // 55296

static constexpr int KSPLIT = 16;
static constexpr int KPER = 4096 / KSPLIT;                // 256
static constexpr int NCHUNK = KPER / 64;                  // 4

static __device__ __forceinline__ void ldsm_x4(uint32_t* r, uint32_t addr)
{
    asm volatile(
        "ldmatrix.sync.aligned.m8n8.x4.shared.b16 {%0,%1,%2,%3}, [%4];"
        : "=r"(r[0]), "=r"(r[1]), "=r"(r[2]), "=r"(r[3]) : "r"(addr));
}

static __device__ __forceinline__ void ldsm_x4_trans(uint32_t* r, uint32_t addr)
{
    asm volatile(
        "ldmatrix.sync.aligned.m8n8.x4.trans.shared.b16 {%0,%1,%2,%3}, [%4];"
        : "=r"(r[0]), "=r"(r[1]), "=r"(r[2]), "=r"(r[3]) : "r"(addr));
}

static __device__ __forceinline__ void mma_bf16(
    float* c, const uint32_t* a, uint32_t b0, uint32_t b1)
{
    asm volatile(
        "mma.sync.aligned.m16n8k16.row.col.f32.bf16.bf16.f32 "
        "{%0,%1,%2,%3}, {%4,%5,%6,%7}, {%8,%9}, {%0,%1,%2,%3};"
        : "+f"(c[0]), "+f"(c[1]), "+f"(c[2]), "+f"(c[3])
        : "r"(a[0]), "r"(a[1]), "r"(a[2]), "r"(a[3]), "r"(b0), "r"(b1));
}

static __device__ __forceinline__ uint32_t f4_to_bf16x2_lo(float a, float b) {
    __nv_bfloat162 p = __float22bfloat162_rn(make_float2(a, b));
    return *reinterpret_cast<uint32_t*>(&p);
}

__global__ __launch_bounds__(256, 2) void ws_gemm_kernel(
    const float* __restrict__ deno, const float* __restrict__ X)
{
    extern __shared__ char sm[];
    const uint32_t smb = smem_u32(sm);

    const int tid = threadIdx.x;
    const int wid = tid >> 5;
    const int lid = tid & 31;
    const int wm = wid >> 1;          // 0..3 : warp M index
    const int wn = wid & 1;           // 0..1 : warp N index
    const int g = lid >> 2;           // group 0..7
    const int tig = lid & 3;          // thread-in-group

    const int row0 = blockIdx.x * 128;
    const int k0 = blockIdx.y * KPER;

    float acc[2][4][4];
#pragma unroll
    for (int i = 0; i < 2; i++)
#pragma unroll
        for (int j = 0; j < 4; j++)
#pragma unroll
            for (int q = 0; q < 4; q++) acc[i][j][q] = 0.0f;

    // ---- prologue: stage chunk 0 into buffer 0 ----
    {
        const int kc = k0;
#pragma unroll
        for (int it = 0; it < 8; it++) {
            int lin = it * 256 + tid;
            int r = lin >> 4, c4 = lin & 15;
            float4 v = *reinterpret_cast<const float4*>(
                deno + (size_t)(row0 + r) * 4096 + kc + c4 * 4);
            uint2 w;
            w.x = f4_to_bf16x2_lo(v.x, v.y);
            w.y = f4_to_bf16x2_lo(v.z, v.w);
            *reinterpret_cast<uint2*>(sm + r * TSTRIDE + c4 * 8) = w;
        }
#pragma unroll
        for (int it = 0; it < 4; it++) {
            int lin = it * 256 + tid;
            int k = lin >> 4, f4 = lin & 15;
            float4 v = *reinterpret_cast<const float4*>(
                X + (size_t)(kc + k) * 64 + f4 * 4);
            uint2 w;
            w.x = f4_to_bf16x2_lo(v.x, v.y);
            w.y = f4_to_bf16x2_lo(v.z, v.w);
            *reinterpret_cast<uint2*>(sm + 2 * ABUF + k * TSTRIDE + f4 * 8) = w;
        }
    }
    __syncthreads();

    // precomputed fragment addresses (byte offsets within a buffer)
    const uint32_t a_off0 = (uint32_t)(wm * 32 + (lid & 7) + ((lid >> 3) & 1) * 8) * TSTRIDE
                          + (uint32_t)(lid >> 4) * 16;
    const uint32_t b_off0 = (uint32_t)((lid & 7) + ((lid >> 3) & 1) * 8) * TSTRIDE
                          + (uint32_t)(wn * 32 + (lid >> 4) * 8) * 2;

#pragma unroll 1
    for (int c = 0; c < NCHUNK; c++) {
        const int buf = c & 1;
        const uint32_t Ab = smb + buf * ABUF;
        const uint32_t Bb = smb + 2 * ABUF + buf * BBUF;

        // issue global loads for next chunk into registers
        float4 aR[8];
        float4 bR[4];
        if (c < NCHUNK - 1) {
            const int kc = k0 + (c + 1) * 64;
#pragma unroll
            for (int it = 0; it < 8; it++) {
                int lin = it * 256 + tid;
                int r = lin >> 4, c4 = lin & 15;
                aR[it] = *reinterpret_cast<const float4*>(
                    deno + (size_t)(row0 + r) * 4096 + kc + c4 * 4);
            }
#pragma unroll
            for (int it = 0; it < 4; it++) {
                int lin = it * 256 + tid;
                int k = lin >> 4, f4 = lin & 15;
                bR[it] = *reinterpret_cast<const float4*>(
                    X + (size_t)(kc + k) * 64 + f4 * 4);
            }
        }

        // compute chunk c: 4 k-steps of 16
#pragma unroll
        for (int ks = 0; ks < 4; ks++) {
            uint32_t af[2][4];
#pragma unroll
            for (int mf = 0; mf < 2; mf++) {
                ldsm_x4(af[mf], Ab + a_off0 + (uint32_t)mf * (16 * TSTRIDE) + ks * 32);
            }
#pragma unroll
            for (int nf2 = 0; nf2 < 2; nf2++) {
                uint32_t br[4];
                ldsm_x4_trans(br, Bb + b_off0 + (uint32_t)(ks * 16) * TSTRIDE
                                   + (uint32_t)(nf2 * 16) * 2);
                mma_bf16(acc[0][nf2 * 2 + 0], af[0], br[0], br[1]);
                mma_bf16(acc[1][nf2 * 2 + 0], af[1], br[0], br[1]);
                mma_bf16(acc[0][nf2 * 2 + 1], af[0], br[2], br[3]);
                mma_bf16(acc[1][nf2 * 2 + 1], af[1], br[2], br[3]);
            }
        }

        // store next chunk into other buffer
        if (c < NCHUNK - 1) {
            const int nb = (c + 1) & 1;
            char* Abp = sm + nb * ABUF;
            char* Bbp = sm + 2 * ABUF + nb * BBUF;
#pragma unroll
            for (int it = 0; it < 8; it++) {
                int lin = it * 256 + tid;
                int r = lin >> 4, c4 = lin & 15;
                uint2 w;
                w.x = f4_to_bf16x2_lo(aR[it].x, aR[it].y);
                w.y = f4_to_bf16x2_lo(aR[it].z, aR[it].w);
                *reinterpret_cast<uint2*>(Abp + r * TSTRIDE + c4 * 8) = w;
            }
#pragma unroll
            for (int it = 0; it < 4; it++) {
                int lin = it * 256 + tid;
                int k = lin >> 4, f4 = lin & 15;
                uint2 w;
                w.x = f4_to_bf16x2_lo(bR[it].x, bR[it].y);
                w.y = f4_to_bf16x2_lo(bR[it].z, bR[it].w);
                *reinterpret_cast<uint2*>(Bbp + k * TSTRIDE + f4 * 8) = w;
            }
        }
        __syncthreads();
    }

    // ---- epilogue: coalesced atomic accumulate into g_acc (1MB, L2-resident) ----
#pragma unroll
    for (int mf = 0; mf < 2; mf++) {
#pragma unroll
        for (int nf = 0; nf < 4; nf++) {
            int row = row0 + wm * 32 + mf * 16 + g;
            int col = wn * 32 + nf * 8 + tig * 2;
            float* p0 = g_acc + (size_t)row * 64 + col;
            float* p1 = g_acc + (size_t)(row + 8) * 64 + col;
            atomicAdd(p0,     acc[mf][nf][0]);
            atomicAdd(p0 + 1, acc[mf][nf][1]);
            atomicAdd(p1,     acc[mf][nf][2]);
            atomicAdd(p1 + 1, acc[mf][nf][3]);
        }
    }
}

// ===================== kernel 2: scatter-add at columns x =====================
// Runs AFTER the D2D memcpy (out = Y) and the gemm (g_acc complete).
// out[r][x[s]] += dt^2 * g_acc[r][s]
__global__ __launch_bounds__(256) void ws_add_kernel(
    const int* __restrict__ xidx, float* __restrict__ out)
{
    __shared__ int xs_s[64];
    if (threadIdx.x < 64) xs_s[threadIdx.x] = xidx[threadIdx.x];
    __syncthreads();

    int gid = blockIdx.x * 256 + threadIdx.x;   // 0 .. 262143
    int row = gid >> 6;
    int s = gid & 63;

    float t = g_acc[gid];
    out[(size_t)row * 4096 + xs_s[s]] += DT2 * t;
}

// ===================== launch =====================
extern "C" void kernel_launch(void* const* d_in, const int* in_sizes, int n_in,
                              void* d_out, int out_size)
{
    const float* Y    = (const float*)d_in[0];
    const float* X    = (const float*)d_in[1];
    const float* deno = (const float*)d_in[2];
    const int*   xi   = (const int*)d_in[3];
    float* out = (float*)d_out;

    cudaFuncSetAttribute(ws_gemm_kernel,
                         cudaFuncAttributeMaxDynamicSharedMemorySize, SMEM_REQ);

    void* accp = nullptr;
    cudaGetSymbolAddress(&accp, g_acc);

    cudaMemsetAsync(accp, 0, 4096 * 64 * sizeof(float));
    ws_gemm_kernel<<<dim3(32, KSPLIT), 256, SMEM_REQ>>>(deno, X);
    cudaMemcpyAsync(out, Y, (size_t)4096 * 4096 * sizeof(float),
                    cudaMemcpyDeviceToDevice);
    ws_add_kernel<<<1024, 256>>>(xi, out);
}

// round 8
// speedup vs baseline: 1.0986x; 1.0986x over previous
#include <cuda_runtime.h>
#include <cuda_bf16.h>
#include <cstdint>

#define DT2 1.0e-6f

// ---------------- device scratch (no allocations allowed) ----------------
__device__ float g_acc[4096 * 64];        // [row*64+s], zeroed per launch, atomic-accumulated
__device__ int g_fast;                    // 1 if x[s] == 64*s for all s
__device__ unsigned char g_inv[4096];     // general-path inverse map

static __device__ __forceinline__ uint32_t smem_u32(const void* p) {
    uint32_t a;
    asm("{ .reg .u64 t; cvta.to.shared.u64 t, %1; cvt.u32.u64 %0, t; }"
        : "=r"(a) : "l"(p));
    return a;
}

// ===================== kernel 0: structure check + inverse map =====================
__global__ void ws_check_kernel(const int* __restrict__ xidx)
{
    const int tid = threadIdx.x;   // 256 threads, 1 block
    if (tid == 0) g_fast = 1;
    reinterpret_cast<int4*>(g_inv)[tid] = make_int4(0, 0, 0, 0);
    __syncthreads();
    if (tid < 64) {
        int xv = xidx[tid];
        g_inv[xv] = (unsigned char)(tid + 1);
        if (xv != tid * 64) atomicExch(&g_fast, 0);
    }
}

// ===================== kernel 1: bf16 mma.sync GEMM =====================
// acc[row0:+128][0:64] += deno[row0:+128, k0:+512] @ X[k0:+512, 0:64]   (atomics)
// grid (32, 8): blockIdx.x = M tile (128 rows), blockIdx.y = K split (512 K)
// 256 threads = 8 warps, warp grid 4(M) x 2(N), warp tile 32x32.
// Kc = 64 per chunk (8 chunks), double buffered, register prefetch.
static constexpr uint32_t TSTRIDE = 144;                  // bytes per row
static constexpr uint32_t ABUF = 128 * TSTRIDE;           // 18432
static constexpr uint32_t BBUF = 64 * TSTRIDE;            // 9216
static constexpr uint32_t SMEM_REQ = 2 * ABUF + 2 * BBUF; // 55296

static constexpr int KSPLIT = 8;
static constexpr int KPER = 4096 / KSPLIT;                // 512
static constexpr int NCHUNK = KPER / 64;                  // 8

static __device__ __forceinline__ void ldsm_x4(uint32_t* r, uint32_t addr)
{
    asm volatile(
        "ldmatrix.sync.aligned.m8n8.x4.shared.b16 {%0,%1,%2,%3}, [%4];"
        : "=r"(r[0]), "=r"(r[1]), "=r"(r[2]), "=r"(r[3]) : "r"(addr));
}

static __device__ __forceinline__ void ldsm_x4_trans(uint32_t* r, uint32_t addr)
{
    asm volatile(
        "ldmatrix.sync.aligned.m8n8.x4.trans.shared.b16 {%0,%1,%2,%3}, [%4];"
        : "=r"(r[0]), "=r"(r[1]), "=r"(r[2]), "=r"(r[3]) : "r"(addr));
}

static __device__ __forceinline__ void mma_bf16(
    float* c, const uint32_t* a, uint32_t b0, uint32_t b1)
{
    asm volatile(
        "mma.sync.aligned.m16n8k16.row.col.f32.bf16.bf16.f32 "
        "{%0,%1,%2,%3}, {%4,%5,%6,%7}, {%8,%9}, {%0,%1,%2,%3};"
        : "+f"(c[0]), "+f"(c[1]), "+f"(c[2]), "+f"(c[3])
        : "r"(a[0]), "r"(a[1]), "r"(a[2]), "r"(a[3]), "r"(b0), "r"(b1));
}

static __device__ __forceinline__ uint32_t f4_to_bf16x2_lo(float a, float b) {
    __nv_bfloat162 p = __float22bfloat162_rn(make_float2(a, b));
    return *reinterpret_cast<uint32_t*>(&p);
}

__global__ __launch_bounds__(256, 2) void ws_gemm_kernel(
    const float* __restrict__ deno, const float* __restrict__ X)
{
    extern __shared__ char sm[];
    const uint32_t smb = smem_u32(sm);

    const int tid = threadIdx.x;
    const int wid = tid >> 5;
    const int lid = tid & 31;
    const int wm = wid >> 1;          // 0..3 : warp M index
    const int wn = wid & 1;           // 0..1 : warp N index
    const int g = lid >> 2;           // group 0..7
    const int tig = lid & 3;          // thread-in-group

    const int row0 = blockIdx.x * 128;
    const int k0 = blockIdx.y * KPER;

    float acc[2][4][4];
#pragma unroll
    for (int i = 0; i < 2; i++)
#pragma unroll
        for (int j = 0; j < 4; j++)
#pragma unroll
            for (int q = 0; q < 4; q++) acc[i][j][q] = 0.0f;

    // ---- prologue: stage chunk 0 into buffer 0 ----
    {
        const int kc = k0;
#pragma unroll
        for (int it = 0; it < 8; it++) {
            int lin = it * 256 + tid;
            int r = lin >> 4, c4 = lin & 15;
            float4 v = *reinterpret_cast<const float4*>(
                deno + (size_t)(row0 + r) * 4096 + kc + c4 * 4);
            uint2 w;
            w.x = f4_to_bf16x2_lo(v.x, v.y);
            w.y = f4_to_bf16x2_lo(v.z, v.w);
            *reinterpret_cast<uint2*>(sm + r * TSTRIDE + c4 * 8) = w;
        }
#pragma unroll
        for (int it = 0; it < 4; it++) {
            int lin = it * 256 + tid;
            int k = lin >> 4, f4 = lin & 15;
            float4 v = *reinterpret_cast<const float4*>(
                X + (size_t)(kc + k) * 64 + f4 * 4);
            uint2 w;
            w.x = f4_to_bf16x2_lo(v.x, v.y);
            w.y = f4_to_bf16x2_lo(v.z, v.w);
            *reinterpret_cast<uint2*>(sm + 2 * ABUF + k * TSTRIDE + f4 * 8) = w;
        }
    }
    __syncthreads();

    // precomputed fragment addresses (byte offsets within a buffer)
    const uint32_t a_off0 = (uint32_t)(wm * 32 + (lid & 7) + ((lid >> 3) & 1) * 8) * TSTRIDE
                          + (uint32_t)(lid >> 4) * 16;
    const uint32_t b_off0 = (uint32_t)((lid & 7) + ((lid >> 3) & 1) * 8) * TSTRIDE
                          + (uint32_t)(wn * 32 + (lid >> 4) * 8) * 2;

#pragma unroll 1
    for (int c = 0; c < NCHUNK; c++) {
        const int buf = c & 1;
        const uint32_t Ab = smb + buf * ABUF;
        const uint32_t Bb = smb + 2 * ABUF + buf * BBUF;

        // issue global loads for next chunk into registers
        float4 aR[8];
        float4 bR[4];
        if (c < NCHUNK - 1) {
            const int kc = k0 + (c + 1) * 64;
#pragma unroll
            for (int it = 0; it < 8; it++) {
                int lin = it * 256 + tid;
                int r = lin >> 4, c4 = lin & 15;
                aR[it] = *reinterpret_cast<const float4*>(
                    deno + (size_t)(row0 + r) * 4096 + kc + c4 * 4);
            }
#pragma unroll
            for (int it = 0; it < 4; it++) {
                int lin = it * 256 + tid;
                int k = lin >> 4, f4 = lin & 15;
                bR[it] = *reinterpret_cast<const float4*>(
                    X + (size_t)(kc + k) * 64 + f4 * 4);
            }
        }

        // compute chunk c: 4 k-steps of 16
#pragma unroll
        for (int ks = 0; ks < 4; ks++) {
            uint32_t af[2][4];
#pragma unroll
            for (int mf = 0; mf < 2; mf++) {
                ldsm_x4(af[mf], Ab + a_off0 + (uint32_t)mf * (16 * TSTRIDE) + ks * 32);
            }
#pragma unroll
            for (int nf2 = 0; nf2 < 2; nf2++) {
                uint32_t br[4];
                ldsm_x4_trans(br, Bb + b_off0 + (uint32_t)(ks * 16) * TSTRIDE
                                   + (uint32_t)(nf2 * 16) * 2);
                mma_bf16(acc[0][nf2 * 2 + 0], af[0], br[0], br[1]);
                mma_bf16(acc[1][nf2 * 2 + 0], af[1], br[0], br[1]);
                mma_bf16(acc[0][nf2 * 2 + 1], af[0], br[2], br[3]);
                mma_bf16(acc[1][nf2 * 2 + 1], af[1], br[2], br[3]);
            }
        }

        // store next chunk into other buffer
        if (c < NCHUNK - 1) {
            const int nb = (c + 1) & 1;
            char* Abp = sm + nb * ABUF;
            char* Bbp = sm + 2 * ABUF + nb * BBUF;
#pragma unroll
            for (int it = 0; it < 8; it++) {
                int lin = it * 256 + tid;
                int r = lin >> 4, c4 = lin & 15;
                uint2 w;
                w.x = f4_to_bf16x2_lo(aR[it].x, aR[it].y);
                w.y = f4_to_bf16x2_lo(aR[it].z, aR[it].w);
                *reinterpret_cast<uint2*>(Abp + r * TSTRIDE + c4 * 8) = w;
            }
#pragma unroll
            for (int it = 0; it < 4; it++) {
                int lin = it * 256 + tid;
                int k = lin >> 4, f4 = lin & 15;
                uint2 w;
                w.x = f4_to_bf16x2_lo(bR[it].x, bR[it].y);
                w.y = f4_to_bf16x2_lo(bR[it].z, bR[it].w);
                *reinterpret_cast<uint2*>(Bbp + k * TSTRIDE + f4 * 8) = w;
            }
        }
        __syncthreads();
    }

    // ---- epilogue: coalesced atomic accumulate into g_acc (1MB, L2-resident) ----
#pragma unroll
    for (int mf = 0; mf < 2; mf++) {
#pragma unroll
        for (int nf = 0; nf < 4; nf++) {
            int row = row0 + wm * 32 + mf * 16 + g;
            int col = wn * 32 + nf * 8 + tig * 2;
            float* p0 = g_acc + (size_t)row * 64 + col;
            float* p1 = g_acc + (size_t)(row + 8) * 64 + col;
            atomicAdd(p0,     acc[mf][nf][0]);
            atomicAdd(p0 + 1, acc[mf][nf][1]);
            atomicAdd(p1,     acc[mf][nf][2]);
            atomicAdd(p1 + 1, acc[mf][nf][3]);
        }
    }
}

// ===================== kernel 2: fused out = Y + dt^2 * scatter(acc) =====================
// Fast path (x[s] == 64*s): touched float4 lanes are exactly c4 % 16 == 0, and
// c4 % 16 == tid % 16, so only threads with tid%16==0 ever add — uniform predicate,
// no table lookups. Loads are batched in groups of 8 to guarantee MLP.
__global__ __launch_bounds__(256) void ws_copy_kernel(
    const float* __restrict__ Y, float* __restrict__ out)
{
    const int tid = threadIdx.x;
    const size_t base = (size_t)blockIdx.x * 4096;
    const int fast = g_fast;

    if (fast) {
        const bool adder = (tid & 15) == 0;
#pragma unroll
        for (int half = 0; half < 2; half++) {
            float4 v[8];
#pragma unroll
            for (int i = 0; i < 8; i++) {
                size_t idx = base + (half * 8 + i) * 256 + tid;
                v[i] = __ldcs(reinterpret_cast<const float4*>(Y) + idx);
            }
            if (adder) {
#pragma unroll
                for (int i = 0; i < 8; i++) {
                    size_t idx = base + (half * 8 + i) * 256 + tid;
                    int row = (int)(idx >> 10);
                    int s = (int)((idx & 1023) >> 4);
                    v[i].x += DT2 * g_acc[row * 64 + s];
                }
            }
#pragma unroll
            for (int i = 0; i < 8; i++) {
                size_t idx = base + (half * 8 + i) * 256 + tid;
                __stcs(reinterpret_cast<float4*>(out) + idx, v[i]);
            }
        }
    } else {
        // general fallback: per-element inverse-table lookup
        __shared__ unsigned char inv_s[4096];
        reinterpret_cast<int4*>(inv_s)[tid] = reinterpret_cast<const int4*>(g_inv)[tid];
        __syncthreads();
#pragma unroll
        for (int it = 0; it < 16; it++) {
            size_t idx = base + it * 256 + tid;
            int row = (int)(idx >> 10);
            int c4 = (int)(idx & 1023);
            float4 v = __ldcs(reinterpret_cast<const float4*>(Y) + idx);
            uchar4 u = *reinterpret_cast<const uchar4*>(&inv_s[c4 * 4]);
            if (u.x | u.y | u.z | u.w) {
                int rb = row * 64;
                if (u.x) v.x += DT2 * g_acc[rb + u.x - 1];
                if (u.y) v.y += DT2 * g_acc[rb + u.y - 1];
                if (u.z) v.z += DT2 * g_acc[rb + u.z - 1];
                if (u.w) v.w += DT2 * g_acc[rb + u.w - 1];
            }
            __stcs(reinterpret_cast<float4*>(out) + idx, v);
        }
    }
}

// ===================== launch =====================
extern "C" void kernel_launch(void* const* d_in, const int* in_sizes, int n_in,
                              void* d_out, int out_size)
{
    const float* Y    = (const float*)d_in[0];
    const float* X    = (const float*)d_in[1];
    const float* deno = (const float*)d_in[2];
    const int*   xi   = (const int*)d_in[3];
    float* out = (float*)d_out;

    cudaFuncSetAttribute(ws_gemm_kernel,
                         cudaFuncAttributeMaxDynamicSharedMemorySize, SMEM_REQ);

    void* accp = nullptr;
    cudaGetSymbolAddress(&accp, g_acc);

    cudaMemsetAsync(accp, 0, 4096 * 64 * sizeof(float));
    ws_check_kernel<<<1, 256>>>(xi);
    ws_gemm_kernel<<<dim3(32, KSPLIT), 256, SMEM_REQ>>>(deno, X);
    ws_copy_kernel<<<1024, 256>>>(Y, out);
}

// round 10
// speedup vs baseline: 1.2385x; 1.1273x over previous
#include <cuda_runtime.h>
#include <cuda_bf16.h>
#include <cstdint>

#define DT2 1.0e-6f

// ---------------- device scratch (no allocations allowed) ----------------
// Zero-initialized at load; ws_copy re-zeroes after each consume, so every
// launch/replay sees acc == 0 (replay-invariant).
__device__ float g_acc[4096 * 64];        // [row*64+s], atomic-accumulated by gemm

static __device__ __forceinline__ uint32_t smem_u32(const void* p) {
    uint32_t a;
    asm("{ .reg .u64 t; cvta.to.shared.u64 t, %1; cvt.u32.u64 %0, t; }"
        : "=r"(a) : "l"(p));
    return a;
}

// ===================== kernel 1: bf16 mma.sync GEMM =====================
// acc[row0:+128][0:64] += deno[row0:+128, k0:+512] @ X[k0:+512, 0:64]   (atomics)
// grid (32, 8): blockIdx.x = M tile (128 rows), blockIdx.y = K split (512 K)
// 256 threads = 8 warps, warp grid 4(M) x 2(N), warp tile 32x32.
// Kc = 64 per chunk (8 chunks), double buffered, register prefetch.
static constexpr uint32_t TSTRIDE = 144;                  // bytes per row
static constexpr uint32_t ABUF = 128 * TSTRIDE;           // 18432
static constexpr uint32_t BBUF = 64 * TSTRIDE;            // 9216
static constexpr uint32_t SMEM_REQ = 2 * ABUF + 2 * BBUF; // 55296

static constexpr int KSPLIT = 8;
static constexpr int KPER = 4096 / KSPLIT;                // 512
static constexpr int NCHUNK = KPER / 64;                  // 8

static __device__ __forceinline__ void ldsm_x4(uint32_t* r, uint32_t addr)
{
    asm volatile(
        "ldmatrix.sync.aligned.m8n8.x4.shared.b16 {%0,%1,%2,%3}, [%4];"
        : "=r"(r[0]), "=r"(r[1]), "=r"(r[2]), "=r"(r[3]) : "r"(addr));
}

static __device__ __forceinline__ void ldsm_x4_trans(uint32_t* r, uint32_t addr)
{
    asm volatile(
        "ldmatrix.sync.aligned.m8n8.x4.trans.shared.b16 {%0,%1,%2,%3}, [%4];"
        : "=r"(r[0]), "=r"(r[1]), "=r"(r[2]), "=r"(r[3]) : "r"(addr));
}

static __device__ __forceinline__ void mma_bf16(
    float* c, const uint32_t* a, uint32_t b0, uint32_t b1)
{
    asm volatile(
        "mma.sync.aligned.m16n8k16.row.col.f32.bf16.bf16.f32 "
        "{%0,%1,%2,%3}, {%4,%5,%6,%7}, {%8,%9}, {%0,%1,%2,%3};"
        : "+f"(c[0]), "+f"(c[1]), "+f"(c[2]), "+f"(c[3])
        : "r"(a[0]), "r"(a[1]), "r"(a[2]), "r"(a[3]), "r"(b0), "r"(b1));
}

static __device__ __forceinline__ uint32_t f4_to_bf16x2_lo(float a, float b) {
    __nv_bfloat162 p = __float22bfloat162_rn(make_float2(a, b));
    return *reinterpret_cast<uint32_t*>(&p);
}

__global__ __launch_bounds__(256, 2) void ws_gemm_kernel(
    const float* __restrict__ deno, const float* __restrict__ X)
{
    extern __shared__ char sm[];
    const uint32_t smb = smem_u32(sm);

    const int tid = threadIdx.x;
    const int wid = tid >> 5;
    const int lid = tid & 31;
    const int wm = wid >> 1;          // 0..3 : warp M index
    const int wn = wid & 1;           // 0..1 : warp N index
    const int g = lid >> 2;           // group 0..7
    const int tig = lid & 3;          // thread-in-group

    const int row0 = blockIdx.x * 128;
    const int k0 = blockIdx.y * KPER;

    float acc[2][4][4];
#pragma unroll
    for (int i = 0; i < 2; i++)
#pragma unroll
        for (int j = 0; j < 4; j++)
#pragma unroll
            for (int q = 0; q < 4; q++) acc[i][j][q] = 0.0f;

    // ---- prologue: stage chunk 0 into buffer 0 ----
    {
        const int kc = k0;
#pragma unroll
        for (int it = 0; it < 8; it++) {
            int lin = it * 256 + tid;
            int r = lin >> 4, c4 = lin & 15;
            float4 v = __ldcs(reinterpret_cast<const float4*>(
                deno + (size_t)(row0 + r) * 4096 + kc + c4 * 4));
            uint2 w;
            w.x = f4_to_bf16x2_lo(v.x, v.y);
            w.y = f4_to_bf16x2_lo(v.z, v.w);
            *reinterpret_cast<uint2*>(sm + r * TSTRIDE + c4 * 8) = w;
        }
#pragma unroll
        for (int it = 0; it < 4; it++) {
            int lin = it * 256 + tid;
            int k = lin >> 4, f4 = lin & 15;
            float4 v = *reinterpret_cast<const float4*>(
                X + (size_t)(kc + k) * 64 + f4 * 4);
            uint2 w;
            w.x = f4_to_bf16x2_lo(v.x, v.y);
            w.y = f4_to_bf16x2_lo(v.z, v.w);
            *reinterpret_cast<uint2*>(sm + 2 * ABUF + k * TSTRIDE + f4 * 8) = w;
        }
    }
    __syncthreads();

    // precomputed fragment addresses (byte offsets within a buffer)
    const uint32_t a_off0 = (uint32_t)(wm * 32 + (lid & 7) + ((lid >> 3) & 1) * 8) * TSTRIDE
                          + (uint32_t)(lid >> 4) * 16;
    const uint32_t b_off0 = (uint32_t)((lid & 7) + ((lid >> 3) & 1) * 8) * TSTRIDE
                          + (uint32_t)(wn * 32 + (lid >> 4) * 8) * 2;

#pragma unroll 1
    for (int c = 0; c < NCHUNK; c++) {
        const int buf = c & 1;
        const uint32_t Ab = smb + buf * ABUF;
        const uint32_t Bb = smb + 2 * ABUF + buf * BBUF;

        // issue global loads for next chunk into registers
        float4 aR[8];
        float4 bR[4];
        if (c < NCHUNK - 1) {
            const int kc = k0 + (c + 1) * 64;
#pragma unroll
            for (int it = 0; it < 8; it++) {
                int lin = it * 256 + tid;
                int r = lin >> 4, c4 = lin & 15;
                aR[it] = __ldcs(reinterpret_cast<const float4*>(
                    deno + (size_t)(row0 + r) * 4096 + kc + c4 * 4));
            }
#pragma unroll
            for (int it = 0; it < 4; it++) {
                int lin = it * 256 + tid;
                int k = lin >> 4, f4 = lin & 15;
                bR[it] = *reinterpret_cast<const float4*>(
                    X + (size_t)(kc + k) * 64 + f4 * 4);
            }
        }

        // compute chunk c: 4 k-steps of 16
#pragma unroll
        for (int ks = 0; ks < 4; ks++) {
            uint32_t af[2][4];
#pragma unroll
            for (int mf = 0; mf < 2; mf++) {
                ldsm_x4(af[mf], Ab + a_off0 + (uint32_t)mf * (16 * TSTRIDE) + ks * 32);
            }
#pragma unroll
            for (int nf2 = 0; nf2 < 2; nf2++) {
                uint32_t br[4];
                ldsm_x4_trans(br, Bb + b_off0 + (uint32_t)(ks * 16) * TSTRIDE
                                   + (uint32_t)(nf2 * 16) * 2);
                mma_bf16(acc[0][nf2 * 2 + 0], af[0], br[0], br[1]);
                mma_bf16(acc[1][nf2 * 2 + 0], af[1], br[0], br[1]);
                mma_bf16(acc[0][nf2 * 2 + 1], af[0], br[2], br[3]);
                mma_bf16(acc[1][nf2 * 2 + 1], af[1], br[2], br[3]);
            }
        }

        // store next chunk into other buffer
        if (c < NCHUNK - 1) {
            const int nb = (c + 1) & 1;
            char* Abp = sm + nb * ABUF;
            char* Bbp = sm + 2 * ABUF + nb * BBUF;
#pragma unroll
            for (int it = 0; it < 8; it++) {
                int lin = it * 256 + tid;
                int r = lin >> 4, c4 = lin & 15;
                uint2 w;
                w.x = f4_to_bf16x2_lo(aR[it].x, aR[it].y);
                w.y = f4_to_bf16x2_lo(aR[it].z, aR[it].w);
                *reinterpret_cast<uint2*>(Abp + r * TSTRIDE + c4 * 8) = w;
            }
#pragma unroll
            for (int it = 0; it < 4; it++) {
                int lin = it * 256 + tid;
                int k = lin >> 4, f4 = lin & 15;
                uint2 w;
                w.x = f4_to_bf16x2_lo(bR[it].x, bR[it].y);
                w.y = f4_to_bf16x2_lo(bR[it].z, bR[it].w);
                *reinterpret_cast<uint2*>(Bbp + k * TSTRIDE + f4 * 8) = w;
            }
        }
        __syncthreads();
    }

    // ---- epilogue: coalesced atomic accumulate into g_acc (1MB, L2-resident) ----
#pragma unroll
    for (int mf = 0; mf < 2; mf++) {
#pragma unroll
        for (int nf = 0; nf < 4; nf++) {
            int row = row0 + wm * 32 + mf * 16 + g;
            int col = wn * 32 + nf * 8 + tig * 2;
            float* p0 = g_acc + (size_t)row * 64 + col;
            float* p1 = g_acc + (size_t)(row + 8) * 64 + col;
            atomicAdd(p0,     acc[mf][nf][0]);
            atomicAdd(p0 + 1, acc[mf][nf][1]);
            atomicAdd(p1,     acc[mf][nf][2]);
            atomicAdd(p1 + 1, acc[mf][nf][3]);
        }
    }
}

// ===================== kernel 2: fused out = Y + dt^2 * scatter(acc) =====================
// Inline structure check (no separate kernel): threads 0..63 verify x[s]==64*s
// against L2-hot xidx; uniform shared flag selects the path. Block b owns output
// rows 4b..4b+3 and zeroes its g_acc slice after consuming it (restores the
// all-zero invariant for the next launch/replay).
__global__ __launch_bounds__(256) void ws_copy_kernel(
    const float* __restrict__ Y, const int* __restrict__ xidx,
    float* __restrict__ out)
{
    __shared__ int fast_s;
    __shared__ unsigned char inv_s[4096];

    const int tid = threadIdx.x;
    const size_t base = (size_t)blockIdx.x * 4096;   // float4 index of first elem

    if (tid == 0) fast_s = 1;
    __syncthreads();
    if (tid < 64) {
        if (__ldg(xidx + tid) != tid * 64) fast_s = 0;
    }
    __syncthreads();

    if (fast_s) {
        const bool adder = (tid & 15) == 0;
#pragma unroll
        for (int half = 0; half < 2; half++) {
            float4 v[8];
#pragma unroll
            for (int i = 0; i < 8; i++) {
                size_t idx = base + (half * 8 + i) * 256 + tid;
                v[i] = __ldcs(reinterpret_cast<const float4*>(Y) + idx);
            }
            if (adder) {
#pragma unroll
                for (int i = 0; i < 8; i++) {
                    size_t idx = base + (half * 8 + i) * 256 + tid;
                    int row = (int)(idx >> 10);
                    int s = (int)((idx & 1023) >> 4);
                    v[i].x += DT2 * g_acc[row * 64 + s];
                }
            }
#pragma unroll
            for (int i = 0; i < 8; i++) {
                size_t idx = base + (half * 8 + i) * 256 + tid;
                __stcs(reinterpret_cast<float4*>(out) + idx, v[i]);
            }
        }
    } else {
        // general fallback: per-element inverse-table lookup
        reinterpret_cast<int4*>(inv_s)[tid] = make_int4(0, 0, 0, 0);
        __syncthreads();
        if (tid < 64) inv_s[__ldg(xidx + tid)] = (unsigned char)(tid + 1);
        __syncthreads();
#pragma unroll
        for (int it = 0; it < 16; it++) {
            size_t idx = base + it * 256 + tid;
            int row = (int)(idx >> 10);
            int c4 = (int)(idx & 1023);
            float4 v = __ldcs(reinterpret_cast<const float4*>(Y) + idx);
            uchar4 u = *reinterpret_cast<const uchar4*>(&inv_s[c4 * 4]);
            if (u.x | u.y | u.z | u.w) {
                int rb = row * 64;
                if (u.x) v.x += DT2 * g_acc[rb + u.x - 1];
                if (u.y) v.y += DT2 * g_acc[rb + u.y - 1];
                if (u.z) v.z += DT2 * g_acc[rb + u.z - 1];
                if (u.w) v.w += DT2 * g_acc[rb + u.w - 1];
            }
            __stcs(reinterpret_cast<float4*>(out) + idx, v);
        }
    }

    // restore acc == 0 for the next launch/replay (this block's 4 rows)
    __syncthreads();
    g_acc[blockIdx.x * 256 + tid] = 0.0f;
}

// ===================== launch =====================
extern "C" void kernel_launch(void* const* d_in, const int* in_sizes, int n_in,
                              void* d_out, int out_size)
{
    const float* Y    = (const float*)d_in[0];
    const float* X    = (const float*)d_in[1];
    const float* deno = (const float*)d_in[2];
    const int*   xi   = (const int*)d_in[3];
    float* out = (float*)d_out;

    cudaFuncSetAttribute(ws_gemm_kernel,
                         cudaFuncAttributeMaxDynamicSharedMemorySize, SMEM_REQ);

    ws_gemm_kernel<<<dim3(32, KSPLIT), 256, SMEM_REQ>>>(deno, X);
    ws_copy_kernel<<<1024, 256>>>(Y, xi, out);
}